// round 7
// baseline (speedup 1.0000x reference)
#include <cuda_runtime.h>
#include <math.h>

#define Bsz 4
#define Ssz 2048
#define Dsz 768
#define Hsz 12
#define HDsz 64
#define BH (Bsz*Hsz)          // 48
#define MROWS (Bsz*Ssz)       // 8192
#define N_QKV (3*Dsz)         // 2304

// ---------------- scratch (no allocations allowed) ----------------
__device__ float g_Q[BH * Ssz * HDsz];   // [b,h,s,hd]
__device__ float g_K[BH * Ssz * HDsz];
__device__ float g_V[BH * Ssz * HDsz];
__device__ float g_attn[MROWS * Dsz];    // [b,s, h*64+hd]
__device__ float g_x[MROWS * Dsz];       // proj + bias + residual

// ---------------- helpers ----------------
__device__ __forceinline__ float tf32hi(float f) {
    unsigned r;
    asm("cvt.rna.tf32.f32 %0, %1;" : "=r"(r) : "f"(f));
    return __uint_as_float(r);
}
__device__ __forceinline__ void mma8(float c[4], const unsigned a[4],
                                     unsigned b0, unsigned b1) {
    asm volatile(
        "mma.sync.aligned.m16n8k8.row.col.f32.tf32.tf32.f32 "
        "{%0,%1,%2,%3}, {%4,%5,%6,%7}, {%8,%9}, {%0,%1,%2,%3};\n"
        : "+f"(c[0]), "+f"(c[1]), "+f"(c[2]), "+f"(c[3])
        : "r"(a[0]), "r"(a[1]), "r"(a[2]), "r"(a[3]), "r"(b0), "r"(b1));
}

// ============================================================
// 3xTF32 GEMM core: block tile 128x64, BK=16, 256 thr, warp tile 32x32.
// acc += Alo*Bhi + Ahi*Blo + Ahi*Bhi  (~fp32 accuracy)
// Shared by both GEMM kernels via a macro-free inline function.
// ============================================================
struct TcOut { float acc[2][4][4]; };

__device__ __forceinline__ void tc3_core(
    const float* __restrict__ A, const float* __restrict__ Bw,
    int NN, int m0, int n0, float acc[2][4][4],
    float AsH[16][132], float AsL[16][132],
    float BsH[16][68],  float BsL[16][68])
{
    const int tid  = threadIdx.x;
    const int lane = tid & 31, wid = tid >> 5;
    const int g = lane >> 2, tig = lane & 3;
    const int wm = wid >> 1, wn = wid & 1;       // warp tile 32x32

    const int mA = tid >> 2, kq = (tid & 3) * 4;    // A: 64 rows x 4 f4 each, two halves
    const float* Ap = A + (size_t)(m0 + mA) * Dsz + kq;
    const int kB = tid >> 4, nq = (tid & 15) * 4;   // B: 16 rows x 16 f4
    const float* Bp = Bw + (size_t)kB * NN + n0 + nq;

#pragma unroll
    for (int i = 0; i < 2; i++)
#pragma unroll
        for (int j = 0; j < 4; j++)
#pragma unroll
            for (int r = 0; r < 4; r++) acc[i][j][r] = 0.f;

#pragma unroll 1
    for (int it = 0; it < Dsz / 16; it++) {
        const int k0 = it * 16;
        float4 ra0 = *(const float4*)(Ap + k0);
        float4 ra1 = *(const float4*)(Ap + k0 + 64 * Dsz);
        float4 rb  = *(const float4*)(Bp + (size_t)k0 * NN);

#pragma unroll
        for (int q = 0; q < 4; q++) {
            float x0 = (&ra0.x)[q], h0 = tf32hi(x0);
            AsH[kq+q][mA]    = h0;
            AsL[kq+q][mA]    = tf32hi(x0 - h0);
            float x1 = (&ra1.x)[q], h1 = tf32hi(x1);
            AsH[kq+q][mA+64] = h1;
            AsL[kq+q][mA+64] = tf32hi(x1 - h1);
            float y = (&rb.x)[q], hb = tf32hi(y);
            BsH[kB][nq+q] = hb;
            BsL[kB][nq+q] = tf32hi(y - hb);
        }
        __syncthreads();

#pragma unroll
        for (int ks = 0; ks < 2; ks++) {
            const int kk = ks * 8 + tig;
            unsigned aH[2][4], aL[2][4];
#pragma unroll
            for (int mf = 0; mf < 2; mf++) {
                const int mm = wm * 32 + mf * 16 + g;
                aH[mf][0] = __float_as_uint(AsH[kk][mm]);
                aH[mf][1] = __float_as_uint(AsH[kk][mm + 8]);
                aH[mf][2] = __float_as_uint(AsH[kk + 4][mm]);
                aH[mf][3] = __float_as_uint(AsH[kk + 4][mm + 8]);
                aL[mf][0] = __float_as_uint(AsL[kk][mm]);
                aL[mf][1] = __float_as_uint(AsL[kk][mm + 8]);
                aL[mf][2] = __float_as_uint(AsL[kk + 4][mm]);
                aL[mf][3] = __float_as_uint(AsL[kk + 4][mm + 8]);
            }
#pragma unroll
            for (int nf = 0; nf < 4; nf++) {
                const int nn = wn * 32 + nf * 8 + g;
                unsigned bH0 = __float_as_uint(BsH[kk][nn]);
                unsigned bH1 = __float_as_uint(BsH[kk + 4][nn]);
                unsigned bL0 = __float_as_uint(BsL[kk][nn]);
                unsigned bL1 = __float_as_uint(BsL[kk + 4][nn]);
                mma8(acc[0][nf], aL[0], bH0, bH1);
                mma8(acc[0][nf], aH[0], bL0, bL1);
                mma8(acc[0][nf], aH[0], bH0, bH1);
                mma8(acc[1][nf], aL[1], bH0, bH1);
                mma8(acc[1][nf], aH[1], bL0, bL1);
                mma8(acc[1][nf], aH[1], bH0, bH1);
            }
        }
        __syncthreads();
    }
}

// ---------------- QKV GEMM -> scatter to g_Q/g_K/g_V ----------------
__global__ void __launch_bounds__(256)
qkv_tc(const float* __restrict__ A, const float* __restrict__ Bw)
{
    __shared__ float AsH[16][132], AsL[16][132];
    __shared__ float BsH[16][68],  BsL[16][68];

    const int m0 = blockIdx.y * 128, n0 = blockIdx.x * 64;
    float acc[2][4][4];
    tc3_core(A, Bw, N_QKV, m0, n0, acc, AsH, AsL, BsH, BsL);

    const int tid = threadIdx.x;
    const int lane = tid & 31, wid = tid >> 5;
    const int g = lane >> 2, tig = lane & 3;
    const int wm = wid >> 1, wn = wid & 1;

    const int nbase = n0 + wn * 32;
    const int which = nbase / Dsz;              // 64-wide block never crosses q/k/v
    const int h = (nbase % Dsz) >> 6;           // 32-wide warp subtile within one head
    const int hd0 = (nbase % Dsz) & 63;
    float* dst = (which == 0) ? g_Q : (which == 1) ? g_K : g_V;
#pragma unroll
    for (int mf = 0; mf < 2; mf++) {
        const int m = m0 + wm * 32 + mf * 16 + g;
        const int b = m >> 11, s = m & 2047;
        float* r0 = dst + ((size_t)(b * Hsz + h) * Ssz + s) * HDsz + hd0;
        float* r1 = r0 + 8 * HDsz;
#pragma unroll
        for (int nf = 0; nf < 4; nf++) {
            const int hd = nf * 8 + tig * 2;
            *(float2*)(r0 + hd) = make_float2(acc[mf][nf][0], acc[mf][nf][1]);
            *(float2*)(r1 + hd) = make_float2(acc[mf][nf][2], acc[mf][nf][3]);
        }
    }
}

// ---------------- proj GEMM -> g_x = acc + bias + resid ----------------
__global__ void __launch_bounds__(256)
proj_tc(const float* __restrict__ Bw, const float* __restrict__ bias,
        const float* __restrict__ resid)
{
    __shared__ float AsH[16][132], AsL[16][132];
    __shared__ float BsH[16][68],  BsL[16][68];

    const int m0 = blockIdx.y * 128, n0 = blockIdx.x * 64;
    float acc[2][4][4];
    tc3_core(g_attn, Bw, Dsz, m0, n0, acc, AsH, AsL, BsH, BsL);

    const int tid = threadIdx.x;
    const int lane = tid & 31, wid = tid >> 5;
    const int g = lane >> 2, tig = lane & 3;
    const int wm = wid >> 1, wn = wid & 1;

#pragma unroll
    for (int mf = 0; mf < 2; mf++) {
        const int m = m0 + wm * 32 + mf * 16 + g;
#pragma unroll
        for (int nf = 0; nf < 4; nf++) {
            const int n = n0 + wn * 32 + nf * 8 + tig * 2;
            float2 bv  = *(const float2*)(bias + n);
            float2 rv0 = *(const float2*)(resid + (size_t)m * Dsz + n);
            float2 rv1 = *(const float2*)(resid + (size_t)(m + 8) * Dsz + n);
            *(float2*)(g_x + (size_t)m * Dsz + n) =
                make_float2(acc[mf][nf][0] + bv.x + rv0.x, acc[mf][nf][1] + bv.y + rv0.y);
            *(float2*)(g_x + (size_t)(m + 8) * Dsz + n) =
                make_float2(acc[mf][nf][2] + bv.x + rv1.x, acc[mf][nf][3] + bv.y + rv1.y);
        }
    }
}

// ---------------- Flash attention (scalar fp32, proven in R1) ----------------
#define SM_QS 0
#define SM_KP (64*65)
#define SM_VS (64*65 + 64*65)
#define ATTN_SMEM_BYTES ((64*65 + 64*65 + 64*64) * 4)

__global__ void fa32_kernel(const float* __restrict__ pad_mask)
{
    extern __shared__ float sm[];
    float* Qs = sm + SM_QS;
    float* KP = sm + SM_KP;
    float* Vs = sm + SM_VS;

    const int tid = threadIdx.x;
    const int tx = tid & 15, ty = tid >> 4;
    const int q0 = blockIdx.x * 64;
    const int bh = blockIdx.y;
    const int b = bh / Hsz;
    const int h = bh % Hsz;

    const float* Qg = g_Q + (size_t)bh * Ssz * HDsz;
    const float* Kg = g_K + (size_t)bh * Ssz * HDsz;
    const float* Vg = g_V + (size_t)bh * Ssz * HDsz;
    const float* mk = pad_mask + b * Ssz;

#pragma unroll
    for (int l = 0; l < 16; l++) {
        int e = tid + l * 256;
        int r = e >> 6, c = e & 63;
        Qs[r * 65 + c] = Qg[(size_t)(q0 + r) * HDsz + c];
    }

    float mr[4], lr[4], O[4][4];
#pragma unroll
    for (int i = 0; i < 4; i++) {
        mr[i] = -1e30f; lr[i] = 0.f;
#pragma unroll
        for (int j = 0; j < 4; j++) O[i][j] = 0.f;
    }

    const float scale = 0.125f;

    for (int kt = 0; kt < Ssz / 64; kt++) {
        const int key0 = kt * 64;
#pragma unroll
        for (int l = 0; l < 16; l++) {
            int e = tid + l * 256;
            int r = e >> 6, c = e & 63;
            KP[c * 65 + r] = Kg[(size_t)(key0 + r) * HDsz + c];
            Vs[r * 64 + c] = Vg[(size_t)(key0 + r) * HDsz + c];
        }
        __syncthreads();

        float s4[4][4];
#pragma unroll
        for (int i = 0; i < 4; i++)
#pragma unroll
            for (int j = 0; j < 4; j++) s4[i][j] = 0.f;
#pragma unroll 16
        for (int k = 0; k < 64; k++) {
            float a[4], bb[4];
#pragma unroll
            for (int i = 0; i < 4; i++) a[i] = Qs[(ty * 4 + i) * 65 + k];
#pragma unroll
            for (int j = 0; j < 4; j++) bb[j] = KP[k * 65 + tx * 4 + j];
#pragma unroll
            for (int i = 0; i < 4; i++)
#pragma unroll
                for (int j = 0; j < 4; j++) s4[i][j] = fmaf(a[i], bb[j], s4[i][j]);
        }

        float mv[4];
#pragma unroll
        for (int j = 0; j < 4; j++) mv[j] = mk[key0 + tx * 4 + j];
#pragma unroll
        for (int i = 0; i < 4; i++)
#pragma unroll
            for (int j = 0; j < 4; j++) {
                float v = s4[i][j] * scale;
                s4[i][j] = v * mv[j] - (1.f - mv[j]) * 1e10f;
            }

        float p4[4][4];
#pragma unroll
        for (int i = 0; i < 4; i++) {
            float tmax = fmaxf(fmaxf(s4[i][0], s4[i][1]), fmaxf(s4[i][2], s4[i][3]));
#pragma unroll
            for (int off = 1; off < 16; off <<= 1)
                tmax = fmaxf(tmax, __shfl_xor_sync(0xffffffffu, tmax, off));
            float mnew = fmaxf(mr[i], tmax);
            float corr = __expf(mr[i] - mnew);
            float rsum = 0.f;
#pragma unroll
            for (int j = 0; j < 4; j++) {
                p4[i][j] = __expf(s4[i][j] - mnew);
                rsum += p4[i][j];
            }
#pragma unroll
            for (int off = 1; off < 16; off <<= 1)
                rsum += __shfl_xor_sync(0xffffffffu, rsum, off);
            lr[i] = lr[i] * corr + rsum;
            mr[i] = mnew;
#pragma unroll
            for (int j = 0; j < 4; j++) O[i][j] *= corr;
        }

        __syncthreads();
#pragma unroll
        for (int i = 0; i < 4; i++)
#pragma unroll
            for (int j = 0; j < 4; j++)
                KP[(ty * 4 + i) * 65 + tx * 4 + j] = p4[i][j];
        __syncthreads();

#pragma unroll 16
        for (int k = 0; k < 64; k++) {
            float pv[4], v[4];
#pragma unroll
            for (int i = 0; i < 4; i++) pv[i] = KP[(ty * 4 + i) * 65 + k];
#pragma unroll
            for (int j = 0; j < 4; j++) v[j] = Vs[k * 64 + tx * 4 + j];
#pragma unroll
            for (int i = 0; i < 4; i++)
#pragma unroll
                for (int j = 0; j < 4; j++) O[i][j] = fmaf(pv[i], v[j], O[i][j]);
        }
        __syncthreads();
    }

#pragma unroll
    for (int i = 0; i < 4; i++) {
        float inv = 1.f / lr[i];
        int s = q0 + ty * 4 + i;
        float* row = g_attn + ((size_t)b * Ssz + s) * Dsz + h * HDsz;
#pragma unroll
        for (int j = 0; j < 4; j++) row[tx * 4 + j] = O[i][j] * inv;
    }
}

// ---------------- LayerNorm over rows of 768 ----------------
__global__ void ln768(const float* __restrict__ gamma,
                      const float* __restrict__ beta,
                      float* __restrict__ out)
{
    __shared__ float red[256];
    const int row = blockIdx.x;
    const int t = threadIdx.x;
    const float* xr = g_x + (size_t)row * Dsz;

    float v[3];
    float s = 0.f;
#pragma unroll
    for (int i = 0; i < 3; i++) { v[i] = xr[t + i * 256]; s += v[i]; }
    red[t] = s; __syncthreads();
#pragma unroll
    for (int off = 128; off > 0; off >>= 1) {
        if (t < off) red[t] += red[t + off];
        __syncthreads();
    }
    float mean = red[0] * (1.f / 768.f);
    __syncthreads();

    float s2 = 0.f;
#pragma unroll
    for (int i = 0; i < 3; i++) { float d = v[i] - mean; s2 += d * d; }
    red[t] = s2; __syncthreads();
#pragma unroll
    for (int off = 128; off > 0; off >>= 1) {
        if (t < off) red[t] += red[t + off];
        __syncthreads();
    }
    float var = red[0] * (1.f / 768.f);
    float inv = rsqrtf(var + 1e-5f);

    float* orow = out + (size_t)row * Dsz;
#pragma unroll
    for (int i = 0; i < 3; i++) {
        int c = t + i * 256;
        orow[c] = (v[i] - mean) * inv * gamma[c] + beta[c];
    }
}

// ---------------- launch ----------------
extern "C" void kernel_launch(void* const* d_in, const int* in_sizes, int n_in,
                              void* d_out, int out_size)
{
    const float* context  = (const float*)d_in[0];
    const float* pad_mask = (const float*)d_in[1];
    const float* w_qkv    = (const float*)d_in[2];
    const float* w_proj   = (const float*)d_in[3];
    const float* b_proj   = (const float*)d_in[4];
    const float* gamma    = (const float*)d_in[5];
    const float* beta     = (const float*)d_in[6];
    float* out = (float*)d_out;

    cudaFuncSetAttribute(fa32_kernel, cudaFuncAttributeMaxDynamicSharedMemorySize,
                         ATTN_SMEM_BYTES);

    qkv_tc<<<dim3(N_QKV / 64, MROWS / 128), 256>>>(context, w_qkv);
    fa32_kernel<<<dim3(Ssz / 64, BH), 256, ATTN_SMEM_BYTES>>>(pad_mask);
    proj_tc<<<dim3(Dsz / 64, MROWS / 128), 256>>>(w_proj, b_proj, context);
    ln768<<<MROWS, 256>>>(gamma, beta, out);
}

// round 10
// speedup vs baseline: 1.8982x; 1.8982x over previous
#include <cuda_runtime.h>
#include <math.h>

#define Bsz 4
#define Ssz 2048
#define Dsz 768
#define Hsz 12
#define HDsz 64
#define BH (Bsz*Hsz)          // 48
#define MROWS (Bsz*Ssz)       // 8192
#define N_QKV (3*Dsz)         // 2304

// ---------------- scratch (no allocations allowed) ----------------
__device__ float g_Q[BH * Ssz * HDsz];   // [b,h,s,hd]
__device__ float g_K[BH * Ssz * HDsz];
__device__ float g_V[BH * Ssz * HDsz];
__device__ float g_attn[MROWS * Dsz];    // [b,s, h*64+hd]
__device__ float g_x[MROWS * Dsz];       // proj + bias + residual

// ---------------- bf16 split helpers (no cuda_bf16.h needed) ----------------
__device__ __forceinline__ float btrunc(float a) {            // bf16 truncate
    return __uint_as_float(__float_as_uint(a) & 0xFFFF0000u);
}
__device__ __forceinline__ unsigned packbf(float ah, float bh) { // both pre-truncated
    return (__float_as_uint(ah) >> 16) | (__float_as_uint(bh) & 0xFFFF0000u);
}
// split consecutive-k pair (a,b) into packed bf16x2 hi and lo words
__device__ __forceinline__ void splitp(float a, float b, unsigned& hp, unsigned& lp) {
    float ah = btrunc(a), bh = btrunc(b);
    hp = packbf(ah, bh);
    lp = packbf(btrunc(a - ah), btrunc(b - bh));
}
__device__ __forceinline__ void mmabf(float c[4], const unsigned a[4],
                                      unsigned b0, unsigned b1) {
    asm volatile(
        "mma.sync.aligned.m16n8k16.row.col.f32.bf16.bf16.f32 "
        "{%0,%1,%2,%3}, {%4,%5,%6,%7}, {%8,%9}, {%0,%1,%2,%3};\n"
        : "+f"(c[0]), "+f"(c[1]), "+f"(c[2]), "+f"(c[3])
        : "r"(a[0]), "r"(a[1]), "r"(a[2]), "r"(a[3]), "r"(b0), "r"(b1));
}

// ============================================================
// bf16x3 GEMM core: block 128x64, BK=32, 256 thr, warp tile 32x32.
// acc += Alo*Bhi + Ahi*Blo + Ahi*Bhi  (~1e-5 accuracy)
// ============================================================
__device__ __forceinline__ void bf3_core(
    const float* __restrict__ A, const float* __restrict__ Bw,
    int NN, int m0, int n0, float acc[2][4][4],
    unsigned AH[128][17], unsigned AL[128][17],
    unsigned BHs[64][17], unsigned BLs[64][17])
{
    const int tid  = threadIdx.x;
    const int lane = tid & 31, wid = tid >> 5;
    const int g = lane >> 2, tig = lane & 3;
    const int wm = wid >> 1, wn = wid & 1;

    const int mA = tid >> 1, kqA = (tid & 1) * 16;   // A: 2 thr/row, 16 k each
    const float* Ap = A + (size_t)(m0 + mA) * Dsz + kqA;
    const int kpB = tid >> 4, nqB = (tid & 15) * 4;  // B: kpair kpB, 4 n each
    const float* Bp = Bw + (size_t)(2 * kpB) * NN + n0 + nqB;

#pragma unroll
    for (int i = 0; i < 2; i++)
#pragma unroll
        for (int j = 0; j < 4; j++)
#pragma unroll
            for (int r = 0; r < 4; r++) acc[i][j][r] = 0.f;

#pragma unroll 1
    for (int it = 0; it < Dsz / 32; it++) {
        const int k0 = it * 32;
        // ---- A: 4 float4 = 16 consecutive k ----
        {
            float4 v0 = *(const float4*)(Ap + k0);
            float4 v1 = *(const float4*)(Ap + k0 + 4);
            float4 v2 = *(const float4*)(Ap + k0 + 8);
            float4 v3 = *(const float4*)(Ap + k0 + 12);
            const int kp = kqA >> 1;
            splitp(v0.x, v0.y, AH[mA][kp+0], AL[mA][kp+0]);
            splitp(v0.z, v0.w, AH[mA][kp+1], AL[mA][kp+1]);
            splitp(v1.x, v1.y, AH[mA][kp+2], AL[mA][kp+2]);
            splitp(v1.z, v1.w, AH[mA][kp+3], AL[mA][kp+3]);
            splitp(v2.x, v2.y, AH[mA][kp+4], AL[mA][kp+4]);
            splitp(v2.z, v2.w, AH[mA][kp+5], AL[mA][kp+5]);
            splitp(v3.x, v3.y, AH[mA][kp+6], AL[mA][kp+6]);
            splitp(v3.z, v3.w, AH[mA][kp+7], AL[mA][kp+7]);
        }
        // ---- B: rows 2*kpB and 2*kpB+1, 4 n ----
        {
            float4 y0 = *(const float4*)(Bp + (size_t)k0 * NN);
            float4 y1 = *(const float4*)(Bp + (size_t)k0 * NN + NN);
            splitp(y0.x, y1.x, BHs[nqB+0][kpB], BLs[nqB+0][kpB]);
            splitp(y0.y, y1.y, BHs[nqB+1][kpB], BLs[nqB+1][kpB]);
            splitp(y0.z, y1.z, BHs[nqB+2][kpB], BLs[nqB+2][kpB]);
            splitp(y0.w, y1.w, BHs[nqB+3][kpB], BLs[nqB+3][kpB]);
        }
        __syncthreads();

#pragma unroll
        for (int ks = 0; ks < 2; ks++) {
            const int kb = ks * 8;
#pragma unroll
            for (int mf = 0; mf < 2; mf++) {
                const int row = wm * 32 + mf * 16 + g;
                unsigned aH[4], aL[4];
                aH[0] = AH[row][kb + tig];       aL[0] = AL[row][kb + tig];
                aH[1] = AH[row + 8][kb + tig];   aL[1] = AL[row + 8][kb + tig];
                aH[2] = AH[row][kb + 4 + tig];   aL[2] = AL[row][kb + 4 + tig];
                aH[3] = AH[row + 8][kb + 4 + tig]; aL[3] = AL[row + 8][kb + 4 + tig];
#pragma unroll
                for (int nf = 0; nf < 4; nf++) {
                    const int n = wn * 32 + nf * 8 + g;
                    unsigned bH0 = BHs[n][kb + tig], bH1 = BHs[n][kb + 4 + tig];
                    unsigned bL0 = BLs[n][kb + tig], bL1 = BLs[n][kb + 4 + tig];
                    mmabf(acc[mf][nf], aL, bH0, bH1);
                    mmabf(acc[mf][nf], aH, bL0, bL1);
                    mmabf(acc[mf][nf], aH, bH0, bH1);
                }
            }
        }
        __syncthreads();
    }
}

// ---------------- QKV GEMM -> scatter to g_Q/g_K/g_V ----------------
__global__ void __launch_bounds__(256)
qkv_b3(const float* __restrict__ A, const float* __restrict__ Bw)
{
    __shared__ unsigned AH[128][17], AL[128][17];
    __shared__ unsigned BHs[64][17], BLs[64][17];

    const int m0 = blockIdx.y * 128, n0 = blockIdx.x * 64;
    float acc[2][4][4];
    bf3_core(A, Bw, N_QKV, m0, n0, acc, AH, AL, BHs, BLs);

    const int tid = threadIdx.x;
    const int lane = tid & 31, wid = tid >> 5;
    const int g = lane >> 2, tig = lane & 3;
    const int wm = wid >> 1, wn = wid & 1;

    const int nbase = n0 + wn * 32;
    const int which = nbase / Dsz;
    const int h = (nbase % Dsz) >> 6;
    const int hd0 = (nbase % Dsz) & 63;          // 0 or 32
    float* dst = (which == 0) ? g_Q : (which == 1) ? g_K : g_V;
#pragma unroll
    for (int mf = 0; mf < 2; mf++) {
        const int m = m0 + wm * 32 + mf * 16 + g;
        const int b = m >> 11, s = m & 2047;
        float* r0 = dst + ((size_t)(b * Hsz + h) * Ssz + s) * HDsz + hd0;
        float* r1 = r0 + 8 * HDsz;
#pragma unroll
        for (int nf = 0; nf < 4; nf++) {
            const int hd = nf * 8 + tig * 2;
            *(float2*)(r0 + hd) = make_float2(acc[mf][nf][0], acc[mf][nf][1]);
            *(float2*)(r1 + hd) = make_float2(acc[mf][nf][2], acc[mf][nf][3]);
        }
    }
}

// ---------------- proj GEMM -> g_x = acc + bias + resid ----------------
__global__ void __launch_bounds__(256)
proj_b3(const float* __restrict__ Bw, const float* __restrict__ bias,
        const float* __restrict__ resid)
{
    __shared__ unsigned AH[128][17], AL[128][17];
    __shared__ unsigned BHs[64][17], BLs[64][17];

    const int m0 = blockIdx.y * 128, n0 = blockIdx.x * 64;
    float acc[2][4][4];
    bf3_core(g_attn, Bw, Dsz, m0, n0, acc, AH, AL, BHs, BLs);

    const int tid = threadIdx.x;
    const int lane = tid & 31, wid = tid >> 5;
    const int g = lane >> 2, tig = lane & 3;
    const int wm = wid >> 1, wn = wid & 1;

#pragma unroll
    for (int mf = 0; mf < 2; mf++) {
        const int m = m0 + wm * 32 + mf * 16 + g;
#pragma unroll
        for (int nf = 0; nf < 4; nf++) {
            const int n = n0 + wn * 32 + nf * 8 + tig * 2;
            float2 bv  = *(const float2*)(bias + n);
            float2 rv0 = *(const float2*)(resid + (size_t)m * Dsz + n);
            float2 rv1 = *(const float2*)(resid + (size_t)(m + 8) * Dsz + n);
            *(float2*)(g_x + (size_t)m * Dsz + n) =
                make_float2(acc[mf][nf][0] + bv.x + rv0.x, acc[mf][nf][1] + bv.y + rv0.y);
            *(float2*)(g_x + (size_t)(m + 8) * Dsz + n) =
                make_float2(acc[mf][nf][2] + bv.x + rv1.x, acc[mf][nf][3] + bv.y + rv1.y);
        }
    }
}

// ---------------- Flash attention (scalar fp32, proven) ----------------
#define SM_QS 0
#define SM_KP (64*65)
#define SM_VS (64*65 + 64*65)
#define ATTN_SMEM_BYTES ((64*65 + 64*65 + 64*64) * 4)

__global__ void fa_sc(const float* __restrict__ pad_mask)
{
    extern __shared__ float sm[];
    float* Qs = sm + SM_QS;
    float* KP = sm + SM_KP;
    float* Vs = sm + SM_VS;

    const int tid = threadIdx.x;
    const int tx = tid & 15, ty = tid >> 4;
    const int q0 = blockIdx.x * 64;
    const int bh = blockIdx.y;
    const int b = bh / Hsz;
    const int h = bh % Hsz;

    const float* Qg = g_Q + (size_t)bh * Ssz * HDsz;
    const float* Kg = g_K + (size_t)bh * Ssz * HDsz;
    const float* Vg = g_V + (size_t)bh * Ssz * HDsz;
    const float* mk = pad_mask + b * Ssz;

#pragma unroll
    for (int l = 0; l < 16; l++) {
        int e = tid + l * 256;
        int r = e >> 6, c = e & 63;
        Qs[r * 65 + c] = Qg[(size_t)(q0 + r) * HDsz + c];
    }

    float mr[4], lr[4], O[4][4];
#pragma unroll
    for (int i = 0; i < 4; i++) {
        mr[i] = -1e30f; lr[i] = 0.f;
#pragma unroll
        for (int j = 0; j < 4; j++) O[i][j] = 0.f;
    }

    const float scale = 0.125f;

    for (int kt = 0; kt < Ssz / 64; kt++) {
        const int key0 = kt * 64;
#pragma unroll
        for (int l = 0; l < 16; l++) {
            int e = tid + l * 256;
            int r = e >> 6, c = e & 63;
            KP[c * 65 + r] = Kg[(size_t)(key0 + r) * HDsz + c];
            Vs[r * 64 + c] = Vg[(size_t)(key0 + r) * HDsz + c];
        }
        __syncthreads();

        float s4[4][4];
#pragma unroll
        for (int i = 0; i < 4; i++)
#pragma unroll
            for (int j = 0; j < 4; j++) s4[i][j] = 0.f;
#pragma unroll 16
        for (int k = 0; k < 64; k++) {
            float a[4], bb[4];
#pragma unroll
            for (int i = 0; i < 4; i++) a[i] = Qs[(ty * 4 + i) * 65 + k];
#pragma unroll
            for (int j = 0; j < 4; j++) bb[j] = KP[k * 65 + tx * 4 + j];
#pragma unroll
            for (int i = 0; i < 4; i++)
#pragma unroll
                for (int j = 0; j < 4; j++) s4[i][j] = fmaf(a[i], bb[j], s4[i][j]);
        }

        float mv[4];
#pragma unroll
        for (int j = 0; j < 4; j++) mv[j] = mk[key0 + tx * 4 + j];
#pragma unroll
        for (int i = 0; i < 4; i++)
#pragma unroll
            for (int j = 0; j < 4; j++) {
                float v = s4[i][j] * scale;
                s4[i][j] = v * mv[j] - (1.f - mv[j]) * 1e10f;
            }

        float p4[4][4];
#pragma unroll
        for (int i = 0; i < 4; i++) {
            float tmax = fmaxf(fmaxf(s4[i][0], s4[i][1]), fmaxf(s4[i][2], s4[i][3]));
#pragma unroll
            for (int off = 1; off < 16; off <<= 1)
                tmax = fmaxf(tmax, __shfl_xor_sync(0xffffffffu, tmax, off));
            float mnew = fmaxf(mr[i], tmax);
            float corr = __expf(mr[i] - mnew);
            float rsum = 0.f;
#pragma unroll
            for (int j = 0; j < 4; j++) {
                p4[i][j] = __expf(s4[i][j] - mnew);
                rsum += p4[i][j];
            }
#pragma unroll
            for (int off = 1; off < 16; off <<= 1)
                rsum += __shfl_xor_sync(0xffffffffu, rsum, off);
            lr[i] = lr[i] * corr + rsum;
            mr[i] = mnew;
#pragma unroll
            for (int j = 0; j < 4; j++) O[i][j] *= corr;
        }

        __syncthreads();
#pragma unroll
        for (int i = 0; i < 4; i++)
#pragma unroll
            for (int j = 0; j < 4; j++)
                KP[(ty * 4 + i) * 65 + tx * 4 + j] = p4[i][j];
        __syncthreads();

#pragma unroll 16
        for (int k = 0; k < 64; k++) {
            float pv[4], v[4];
#pragma unroll
            for (int i = 0; i < 4; i++) pv[i] = KP[(ty * 4 + i) * 65 + k];
#pragma unroll
            for (int j = 0; j < 4; j++) v[j] = Vs[k * 64 + tx * 4 + j];
#pragma unroll
            for (int i = 0; i < 4; i++)
#pragma unroll
                for (int j = 0; j < 4; j++) O[i][j] = fmaf(pv[i], v[j], O[i][j]);
        }
        __syncthreads();
    }

#pragma unroll
    for (int i = 0; i < 4; i++) {
        float inv = 1.f / lr[i];
        int s = q0 + ty * 4 + i;
        float* row = g_attn + ((size_t)b * Ssz + s) * Dsz + h * HDsz;
#pragma unroll
        for (int j = 0; j < 4; j++) row[tx * 4 + j] = O[i][j] * inv;
    }
}

// ---------------- LayerNorm over rows of 768 ----------------
__global__ void ln_v2(const float* __restrict__ gamma,
                      const float* __restrict__ beta,
                      float* __restrict__ out)
{
    __shared__ float red[256];
    const int row = blockIdx.x;
    const int t = threadIdx.x;
    const float* xr = g_x + (size_t)row * Dsz;

    float v[3];
    float s = 0.f;
#pragma unroll
    for (int i = 0; i < 3; i++) { v[i] = xr[t + i * 256]; s += v[i]; }
    red[t] = s; __syncthreads();
#pragma unroll
    for (int off = 128; off > 0; off >>= 1) {
        if (t < off) red[t] += red[t + off];
        __syncthreads();
    }
    float mean = red[0] * (1.f / 768.f);
    __syncthreads();

    float s2 = 0.f;
#pragma unroll
    for (int i = 0; i < 3; i++) { float d = v[i] - mean; s2 += d * d; }
    red[t] = s2; __syncthreads();
#pragma unroll
    for (int off = 128; off > 0; off >>= 1) {
        if (t < off) red[t] += red[t + off];
        __syncthreads();
    }
    float var = red[0] * (1.f / 768.f);
    float inv = rsqrtf(var + 1e-5f);

    float* orow = out + (size_t)row * Dsz;
#pragma unroll
    for (int i = 0; i < 3; i++) {
        int c = t + i * 256;
        orow[c] = (v[i] - mean) * inv * gamma[c] + beta[c];
    }
}

// ---------------- launch ----------------
extern "C" void kernel_launch(void* const* d_in, const int* in_sizes, int n_in,
                              void* d_out, int out_size)
{
    const float* context  = (const float*)d_in[0];
    const float* pad_mask = (const float*)d_in[1];
    const float* w_qkv    = (const float*)d_in[2];
    const float* w_proj   = (const float*)d_in[3];
    const float* b_proj   = (const float*)d_in[4];
    const float* gamma    = (const float*)d_in[5];
    const float* beta     = (const float*)d_in[6];
    float* out = (float*)d_out;

    cudaFuncSetAttribute(fa_sc, cudaFuncAttributeMaxDynamicSharedMemorySize,
                         ATTN_SMEM_BYTES);

    qkv_b3<<<dim3(N_QKV / 64, MROWS / 128), 256>>>(context, w_qkv);
    fa_sc<<<dim3(Ssz / 64, BH), 256, ATTN_SMEM_BYTES>>>(pad_mask);
    proj_b3<<<dim3(Dsz / 64, MROWS / 128), 256>>>(w_proj, b_proj, context);
    ln_v2<<<MROWS, 256>>>(gamma, beta, out);
}

// round 12
// speedup vs baseline: 2.4226x; 1.2762x over previous
#include <cuda_runtime.h>
#include <math.h>

#define Bsz 4
#define Ssz 2048
#define Dsz 768
#define Hsz 12
#define HDsz 64
#define BH (Bsz*Hsz)          // 48
#define MROWS (Bsz*Ssz)       // 8192
#define N_QKV (3*Dsz)         // 2304

// ---------------- scratch (no allocations allowed) ----------------
__device__ float g_Q[BH * Ssz * HDsz];   // [b,h,s,hd]
__device__ float g_K[BH * Ssz * HDsz];
__device__ float g_V[BH * Ssz * HDsz];
__device__ float g_attn[MROWS * Dsz];    // [b,s, h*64+hd]
__device__ float g_x[MROWS * Dsz];       // proj + bias + residual

// ---------------- bf16 split helpers ----------------
__device__ __forceinline__ float btrunc(float a) {            // bf16 truncate
    return __uint_as_float(__float_as_uint(a) & 0xFFFF0000u);
}
__device__ __forceinline__ unsigned packbf(float ah, float bh) { // both pre-truncated
    return (__float_as_uint(ah) >> 16) | (__float_as_uint(bh) & 0xFFFF0000u);
}
// split consecutive-k pair (a,b) into packed bf16x2 hi and lo words
__device__ __forceinline__ void splitp(float a, float b, unsigned& hp, unsigned& lp) {
    float ah = btrunc(a), bh = btrunc(b);
    hp = packbf(ah, bh);
    lp = packbf(btrunc(a - ah), btrunc(b - bh));
}
__device__ __forceinline__ void mmabf(float c[4], const unsigned a[4],
                                      unsigned b0, unsigned b1) {
    asm volatile(
        "mma.sync.aligned.m16n8k16.row.col.f32.bf16.bf16.f32 "
        "{%0,%1,%2,%3}, {%4,%5,%6,%7}, {%8,%9}, {%0,%1,%2,%3};\n"
        : "+f"(c[0]), "+f"(c[1]), "+f"(c[2]), "+f"(c[3])
        : "r"(a[0]), "r"(a[1]), "r"(a[2]), "r"(a[3]), "r"(b0), "r"(b1));
}

// ============================================================
// bf16x3 GEMM core: block 128x64, BK=32, 256 thr, warp tile 32x32.
// (proven build + pass in R10)
// ============================================================
__device__ __forceinline__ void bf3_core(
    const float* __restrict__ A, const float* __restrict__ Bw,
    int NN, int m0, int n0, float acc[2][4][4],
    unsigned AH[128][17], unsigned AL[128][17],
    unsigned BHs[64][17], unsigned BLs[64][17])
{
    const int tid  = threadIdx.x;
    const int lane = tid & 31, wid = tid >> 5;
    const int g = lane >> 2, tig = lane & 3;
    const int wm = wid >> 1, wn = wid & 1;

    const int mA = tid >> 1, kqA = (tid & 1) * 16;
    const float* Ap = A + (size_t)(m0 + mA) * Dsz + kqA;
    const int kpB = tid >> 4, nqB = (tid & 15) * 4;
    const float* Bp = Bw + (size_t)(2 * kpB) * NN + n0 + nqB;

#pragma unroll
    for (int i = 0; i < 2; i++)
#pragma unroll
        for (int j = 0; j < 4; j++)
#pragma unroll
            for (int r = 0; r < 4; r++) acc[i][j][r] = 0.f;

#pragma unroll 1
    for (int it = 0; it < Dsz / 32; it++) {
        const int k0 = it * 32;
        {
            float4 v0 = *(const float4*)(Ap + k0);
            float4 v1 = *(const float4*)(Ap + k0 + 4);
            float4 v2 = *(const float4*)(Ap + k0 + 8);
            float4 v3 = *(const float4*)(Ap + k0 + 12);
            const int kp = kqA >> 1;
            splitp(v0.x, v0.y, AH[mA][kp+0], AL[mA][kp+0]);
            splitp(v0.z, v0.w, AH[mA][kp+1], AL[mA][kp+1]);
            splitp(v1.x, v1.y, AH[mA][kp+2], AL[mA][kp+2]);
            splitp(v1.z, v1.w, AH[mA][kp+3], AL[mA][kp+3]);
            splitp(v2.x, v2.y, AH[mA][kp+4], AL[mA][kp+4]);
            splitp(v2.z, v2.w, AH[mA][kp+5], AL[mA][kp+5]);
            splitp(v3.x, v3.y, AH[mA][kp+6], AL[mA][kp+6]);
            splitp(v3.z, v3.w, AH[mA][kp+7], AL[mA][kp+7]);
        }
        {
            float4 y0 = *(const float4*)(Bp + (size_t)k0 * NN);
            float4 y1 = *(const float4*)(Bp + (size_t)k0 * NN + NN);
            splitp(y0.x, y1.x, BHs[nqB+0][kpB], BLs[nqB+0][kpB]);
            splitp(y0.y, y1.y, BHs[nqB+1][kpB], BLs[nqB+1][kpB]);
            splitp(y0.z, y1.z, BHs[nqB+2][kpB], BLs[nqB+2][kpB]);
            splitp(y0.w, y1.w, BHs[nqB+3][kpB], BLs[nqB+3][kpB]);
        }
        __syncthreads();

#pragma unroll
        for (int ks = 0; ks < 2; ks++) {
            const int kb = ks * 8;
#pragma unroll
            for (int mf = 0; mf < 2; mf++) {
                const int row = wm * 32 + mf * 16 + g;
                unsigned aH[4], aL[4];
                aH[0] = AH[row][kb + tig];         aL[0] = AL[row][kb + tig];
                aH[1] = AH[row + 8][kb + tig];     aL[1] = AL[row + 8][kb + tig];
                aH[2] = AH[row][kb + 4 + tig];     aL[2] = AL[row][kb + 4 + tig];
                aH[3] = AH[row + 8][kb + 4 + tig]; aL[3] = AL[row + 8][kb + 4 + tig];
#pragma unroll
                for (int nf = 0; nf < 4; nf++) {
                    const int n = wn * 32 + nf * 8 + g;
                    unsigned bH0 = BHs[n][kb + tig], bH1 = BHs[n][kb + 4 + tig];
                    unsigned bL0 = BLs[n][kb + tig], bL1 = BLs[n][kb + 4 + tig];
                    mmabf(acc[mf][nf], aL, bH0, bH1);
                    mmabf(acc[mf][nf], aH, bL0, bL1);
                    mmabf(acc[mf][nf], aH, bH0, bH1);
                }
            }
        }
        __syncthreads();
    }
}

// ---------------- QKV GEMM -> scatter to g_Q/g_K/g_V ----------------
__global__ void __launch_bounds__(256)
qkv_b3(const float* __restrict__ A, const float* __restrict__ Bw)
{
    __shared__ unsigned AH[128][17], AL[128][17];
    __shared__ unsigned BHs[64][17], BLs[64][17];

    const int m0 = blockIdx.y * 128, n0 = blockIdx.x * 64;
    float acc[2][4][4];
    bf3_core(A, Bw, N_QKV, m0, n0, acc, AH, AL, BHs, BLs);

    const int tid = threadIdx.x;
    const int lane = tid & 31, wid = tid >> 5;
    const int g = lane >> 2, tig = lane & 3;
    const int wm = wid >> 1, wn = wid & 1;

    const int nbase = n0 + wn * 32;
    const int which = nbase / Dsz;
    const int h = (nbase % Dsz) >> 6;
    const int hd0 = (nbase % Dsz) & 63;
    float* dst = (which == 0) ? g_Q : (which == 1) ? g_K : g_V;
#pragma unroll
    for (int mf = 0; mf < 2; mf++) {
        const int m = m0 + wm * 32 + mf * 16 + g;
        const int b = m >> 11, s = m & 2047;
        float* r0 = dst + ((size_t)(b * Hsz + h) * Ssz + s) * HDsz + hd0;
        float* r1 = r0 + 8 * HDsz;
#pragma unroll
        for (int nf = 0; nf < 4; nf++) {
            const int hd = nf * 8 + tig * 2;
            *(float2*)(r0 + hd) = make_float2(acc[mf][nf][0], acc[mf][nf][1]);
            *(float2*)(r1 + hd) = make_float2(acc[mf][nf][2], acc[mf][nf][3]);
        }
    }
}

// ---------------- proj GEMM -> g_x = acc + bias + resid ----------------
__global__ void __launch_bounds__(256)
proj_b3(const float* __restrict__ Bw, const float* __restrict__ bias,
        const float* __restrict__ resid)
{
    __shared__ unsigned AH[128][17], AL[128][17];
    __shared__ unsigned BHs[64][17], BLs[64][17];

    const int m0 = blockIdx.y * 128, n0 = blockIdx.x * 64;
    float acc[2][4][4];
    bf3_core(g_attn, Bw, Dsz, m0, n0, acc, AH, AL, BHs, BLs);

    const int tid = threadIdx.x;
    const int lane = tid & 31, wid = tid >> 5;
    const int g = lane >> 2, tig = lane & 3;
    const int wm = wid >> 1, wn = wid & 1;

#pragma unroll
    for (int mf = 0; mf < 2; mf++) {
        const int m = m0 + wm * 32 + mf * 16 + g;
#pragma unroll
        for (int nf = 0; nf < 4; nf++) {
            const int n = n0 + wn * 32 + nf * 8 + tig * 2;
            float2 bv  = *(const float2*)(bias + n);
            float2 rv0 = *(const float2*)(resid + (size_t)m * Dsz + n);
            float2 rv1 = *(const float2*)(resid + (size_t)(m + 8) * Dsz + n);
            *(float2*)(g_x + (size_t)m * Dsz + n) =
                make_float2(acc[mf][nf][0] + bv.x + rv0.x, acc[mf][nf][1] + bv.y + rv0.y);
            *(float2*)(g_x + (size_t)(m + 8) * Dsz + n) =
                make_float2(acc[mf][nf][2] + bv.x + rv1.x, acc[mf][nf][3] + bv.y + rv1.y);
        }
    }
}

// ============================================================
// Flash attention, bf16x3 HMMA. 128 thr (4 warps), q-tile 64, k-tile 64.
// P stays in registers (S C-frag pairs == P A-frag k-pairs).
// ks-loops are unroll-1 to bound code size (build budget).
// ============================================================
#define ATTN_SMEM_BYTES ((4 * 64 * 33 + 64 * 66 + 64) * 4)  // 50944 B

__global__ void __launch_bounds__(128)
fa_tc(const float* __restrict__ pad_mask)
{
    extern __shared__ unsigned smu[];
    unsigned* QsH = smu;                    // [64][33] packed k-pairs
    unsigned* QsL = QsH + 64 * 33;
    unsigned* KsH = QsL + 64 * 33;
    unsigned* KsL = KsH + 64 * 33;
    unsigned short* VtH = (unsigned short*)(KsL + 64 * 33);  // bf16 [hd=64][66]
    unsigned short* VtL = VtH + 64 * 66;
    float* msk = (float*)(smu + 4 * 64 * 33 + 64 * 66);

    const int tid  = threadIdx.x;
    const int lane = tid & 31, wid = tid >> 5;
    const int g = lane >> 2, tig = lane & 3;
    const int qw = wid * 16;
    const int q0 = blockIdx.x * 64;
    const int bh = blockIdx.y;
    const int b = bh / Hsz, h = bh % Hsz;

    const float* Qg = g_Q + ((size_t)bh * Ssz + q0) * HDsz;
    const float* Kg = g_K + (size_t)bh * Ssz * HDsz;
    const float* Vg = g_V + (size_t)bh * Ssz * HDsz;
    const float* mk = pad_mask + b * Ssz;

    // ---- load Q tile, split into packed hi/lo k-pairs ----
#pragma unroll
    for (int i = 0; i < 8; i++) {
        int idx = tid + i * 128;
        int r = idx >> 4, c4 = (idx & 15) * 4;
        float4 v = *(const float4*)(Qg + r * HDsz + c4);
        int kp = r * 33 + (c4 >> 1);
        splitp(v.x, v.y, QsH[kp],     QsL[kp]);
        splitp(v.z, v.w, QsH[kp + 1], QsL[kp + 1]);
    }

    float O[8][4];
#pragma unroll
    for (int i = 0; i < 8; i++)
#pragma unroll
        for (int j = 0; j < 4; j++) O[i][j] = 0.f;
    float m0r = -1e30f, m1r = -1e30f, l0 = 0.f, l1 = 0.f;
    const float scale = 0.125f;

#pragma unroll 1
    for (int kt = 0; kt < Ssz / 64; kt++) {
        const int key0 = kt * 64;
        __syncthreads();   // prior tile's smem reads done
#pragma unroll
        for (int i = 0; i < 8; i++) {
            int idx = tid + i * 128;
            int r = idx >> 4, c4 = (idx & 15) * 4;
            float4 kv = *(const float4*)(Kg + (size_t)(key0 + r) * HDsz + c4);
            int kp = r * 33 + (c4 >> 1);
            splitp(kv.x, kv.y, KsH[kp],     KsL[kp]);
            splitp(kv.z, kv.w, KsH[kp + 1], KsL[kp + 1]);
            float4 vv = *(const float4*)(Vg + (size_t)(key0 + r) * HDsz + c4);
#pragma unroll
            for (int q = 0; q < 4; q++) {
                float x = (&vv.x)[q];
                float hh = btrunc(x);
                VtH[(c4 + q) * 66 + r] = (unsigned short)(__float_as_uint(hh) >> 16);
                VtL[(c4 + q) * 66 + r] = (unsigned short)(__float_as_uint(btrunc(x - hh)) >> 16);
            }
        }
        if (tid < 64) msk[tid] = mk[key0 + tid];
        __syncthreads();

        // ---- S = Q @ K^T (bf16x3) ----
        float sacc[8][4];
#pragma unroll
        for (int i = 0; i < 8; i++)
#pragma unroll
            for (int j = 0; j < 4; j++) sacc[i][j] = 0.f;
#pragma unroll 1
        for (int ks = 0; ks < 4; ks++) {
            const int kb = ks * 8;
            const int row = qw + g;
            unsigned aH[4], aL[4];
            aH[0] = QsH[row * 33 + kb + tig];
            aH[1] = QsH[(row + 8) * 33 + kb + tig];
            aH[2] = QsH[row * 33 + kb + 4 + tig];
            aH[3] = QsH[(row + 8) * 33 + kb + 4 + tig];
            aL[0] = QsL[row * 33 + kb + tig];
            aL[1] = QsL[(row + 8) * 33 + kb + tig];
            aL[2] = QsL[row * 33 + kb + 4 + tig];
            aL[3] = QsL[(row + 8) * 33 + kb + 4 + tig];
#pragma unroll
            for (int nf = 0; nf < 8; nf++) {
                const int n = nf * 8 + g;
                unsigned bH0 = KsH[n * 33 + kb + tig];
                unsigned bH1 = KsH[n * 33 + kb + 4 + tig];
                unsigned bL0 = KsL[n * 33 + kb + tig];
                unsigned bL1 = KsL[n * 33 + kb + 4 + tig];
                mmabf(sacc[nf], aL, bH0, bH1);
                mmabf(sacc[nf], aH, bL0, bL1);
                mmabf(sacc[nf], aH, bH0, bH1);
            }
        }

        // ---- mask + scale ----
#pragma unroll
        for (int nf = 0; nf < 8; nf++) {
            float mv0 = msk[nf * 8 + tig * 2];
            float mv1 = msk[nf * 8 + tig * 2 + 1];
            sacc[nf][0] = sacc[nf][0] * scale * mv0 - (1.f - mv0) * 1e10f;
            sacc[nf][1] = sacc[nf][1] * scale * mv1 - (1.f - mv1) * 1e10f;
            sacc[nf][2] = sacc[nf][2] * scale * mv0 - (1.f - mv0) * 1e10f;
            sacc[nf][3] = sacc[nf][3] * scale * mv1 - (1.f - mv1) * 1e10f;
        }

        // ---- online softmax (rows g and g+8) ----
        float tm0 = -1e30f, tm1 = -1e30f;
#pragma unroll
        for (int nf = 0; nf < 8; nf++) {
            tm0 = fmaxf(tm0, fmaxf(sacc[nf][0], sacc[nf][1]));
            tm1 = fmaxf(tm1, fmaxf(sacc[nf][2], sacc[nf][3]));
        }
        tm0 = fmaxf(tm0, __shfl_xor_sync(0xffffffffu, tm0, 1));
        tm0 = fmaxf(tm0, __shfl_xor_sync(0xffffffffu, tm0, 2));
        tm1 = fmaxf(tm1, __shfl_xor_sync(0xffffffffu, tm1, 1));
        tm1 = fmaxf(tm1, __shfl_xor_sync(0xffffffffu, tm1, 2));
        float mn0 = fmaxf(m0r, tm0), mn1 = fmaxf(m1r, tm1);
        float c0 = __expf(m0r - mn0), c1 = __expf(m1r - mn1);
        float s0 = 0.f, s1 = 0.f;
#pragma unroll
        for (int nf = 0; nf < 8; nf++) {
            sacc[nf][0] = __expf(sacc[nf][0] - mn0);
            sacc[nf][1] = __expf(sacc[nf][1] - mn0);
            sacc[nf][2] = __expf(sacc[nf][2] - mn1);
            sacc[nf][3] = __expf(sacc[nf][3] - mn1);
            s0 += sacc[nf][0] + sacc[nf][1];
            s1 += sacc[nf][2] + sacc[nf][3];
        }
        s0 += __shfl_xor_sync(0xffffffffu, s0, 1);
        s0 += __shfl_xor_sync(0xffffffffu, s0, 2);
        s1 += __shfl_xor_sync(0xffffffffu, s1, 1);
        s1 += __shfl_xor_sync(0xffffffffu, s1, 2);
        l0 = l0 * c0 + s0;
        l1 = l1 * c1 + s1;
        m0r = mn0; m1r = mn1;
#pragma unroll
        for (int nf = 0; nf < 8; nf++) {
            O[nf][0] *= c0; O[nf][1] *= c0;
            O[nf][2] *= c1; O[nf][3] *= c1;
        }

        // ---- O += P @ V (bf16x3, P in registers) ----
#pragma unroll 1
        for (int ks = 0; ks < 4; ks++) {
            unsigned aPH[4], aPL[4];
            splitp(sacc[2 * ks][0],     sacc[2 * ks][1],     aPH[0], aPL[0]); // row g
            splitp(sacc[2 * ks][2],     sacc[2 * ks][3],     aPH[1], aPL[1]); // row g+8
            splitp(sacc[2 * ks + 1][0], sacc[2 * ks + 1][1], aPH[2], aPL[2]);
            splitp(sacc[2 * ks + 1][2], sacc[2 * ks + 1][3], aPH[3], aPL[3]);
            const int kb = ks * 16 + 2 * tig;
#pragma unroll
            for (int nf = 0; nf < 8; nf++) {
                const int n = nf * 8 + g;
                unsigned bH0 = *(const unsigned*)(VtH + n * 66 + kb);
                unsigned bH1 = *(const unsigned*)(VtH + n * 66 + kb + 8);
                unsigned bL0 = *(const unsigned*)(VtL + n * 66 + kb);
                unsigned bL1 = *(const unsigned*)(VtL + n * 66 + kb + 8);
                mmabf(O[nf], aPL, bH0, bH1);
                mmabf(O[nf], aPH, bL0, bL1);
                mmabf(O[nf], aPH, bH0, bH1);
            }
        }
    }

    // ---- epilogue -> g_attn[b,s,h*64+hd] ----
    const float inv0 = 1.f / l0, inv1 = 1.f / l1;
    const int s0r = q0 + qw + g, s1r = s0r + 8;
    float* r0 = g_attn + ((size_t)b * Ssz + s0r) * Dsz + h * HDsz;
    float* r1 = g_attn + ((size_t)b * Ssz + s1r) * Dsz + h * HDsz;
#pragma unroll
    for (int nf = 0; nf < 8; nf++) {
        const int hd = nf * 8 + tig * 2;
        *(float2*)(r0 + hd) = make_float2(O[nf][0] * inv0, O[nf][1] * inv0);
        *(float2*)(r1 + hd) = make_float2(O[nf][2] * inv1, O[nf][3] * inv1);
    }
}

// ---------------- LayerNorm over rows of 768 ----------------
__global__ void ln_v2(const float* __restrict__ gamma,
                      const float* __restrict__ beta,
                      float* __restrict__ out)
{
    __shared__ float red[256];
    const int row = blockIdx.x;
    const int t = threadIdx.x;
    const float* xr = g_x + (size_t)row * Dsz;

    float v[3];
    float s = 0.f;
#pragma unroll
    for (int i = 0; i < 3; i++) { v[i] = xr[t + i * 256]; s += v[i]; }
    red[t] = s; __syncthreads();
#pragma unroll
    for (int off = 128; off > 0; off >>= 1) {
        if (t < off) red[t] += red[t + off];
        __syncthreads();
    }
    float mean = red[0] * (1.f / 768.f);
    __syncthreads();

    float s2 = 0.f;
#pragma unroll
    for (int i = 0; i < 3; i++) { float d = v[i] - mean; s2 += d * d; }
    red[t] = s2; __syncthreads();
#pragma unroll
    for (int off = 128; off > 0; off >>= 1) {
        if (t < off) red[t] += red[t + off];
        __syncthreads();
    }
    float var = red[0] * (1.f / 768.f);
    float inv = rsqrtf(var + 1e-5f);

    float* orow = out + (size_t)row * Dsz;
#pragma unroll
    for (int i = 0; i < 3; i++) {
        int c = t + i * 256;
        orow[c] = (v[i] - mean) * inv * gamma[c] + beta[c];
    }
}

// ---------------- launch ----------------
extern "C" void kernel_launch(void* const* d_in, const int* in_sizes, int n_in,
                              void* d_out, int out_size)
{
    const float* context  = (const float*)d_in[0];
    const float* pad_mask = (const float*)d_in[1];
    const float* w_qkv    = (const float*)d_in[2];
    const float* w_proj   = (const float*)d_in[3];
    const float* b_proj   = (const float*)d_in[4];
    const float* gamma    = (const float*)d_in[5];
    const float* beta     = (const float*)d_in[6];
    float* out = (float*)d_out;

    cudaFuncSetAttribute(fa_tc, cudaFuncAttributeMaxDynamicSharedMemorySize,
                         ATTN_SMEM_BYTES);

    qkv_b3<<<dim3(N_QKV / 64, MROWS / 128), 256>>>(context, w_qkv);
    fa_tc<<<dim3(Ssz / 64, BH), 128, ATTN_SMEM_BYTES>>>(pad_mask);
    proj_b3<<<dim3(Dsz / 64, MROWS / 128), 256>>>(w_proj, b_proj, context);
    ln_v2<<<MROWS, 256>>>(gamma, beta, out);
}

// round 13
// speedup vs baseline: 2.4642x; 1.0172x over previous
#include <cuda_runtime.h>
#include <math.h>

#define Bsz 4
#define Ssz 2048
#define Dsz 768
#define Hsz 12
#define HDsz 64
#define BH (Bsz*Hsz)          // 48
#define MROWS (Bsz*Ssz)       // 8192
#define N_QKV (3*Dsz)         // 2304

// ---------------- scratch (no allocations allowed) ----------------
__device__ float g_Q[BH * Ssz * HDsz];   // [b,h,s,hd]
__device__ float g_K[BH * Ssz * HDsz];
__device__ float g_V[BH * Ssz * HDsz];
__device__ float g_attn[MROWS * Dsz];    // [b,s, h*64+hd]
__device__ float g_x[MROWS * Dsz];       // proj + bias + residual

// ---------------- bf16 split helpers ----------------
__device__ __forceinline__ float btrunc(float a) {            // bf16 truncate
    return __uint_as_float(__float_as_uint(a) & 0xFFFF0000u);
}
__device__ __forceinline__ unsigned packbf(float ah, float bh) { // both pre-truncated
    return (__float_as_uint(ah) >> 16) | (__float_as_uint(bh) & 0xFFFF0000u);
}
__device__ __forceinline__ void splitp(float a, float b, unsigned& hp, unsigned& lp) {
    float ah = btrunc(a), bh = btrunc(b);
    hp = packbf(ah, bh);
    lp = packbf(btrunc(a - ah), btrunc(b - bh));
}
__device__ __forceinline__ void mmabf(float c[4], const unsigned a[4],
                                      unsigned b0, unsigned b1) {
    asm volatile(
        "mma.sync.aligned.m16n8k16.row.col.f32.bf16.bf16.f32 "
        "{%0,%1,%2,%3}, {%4,%5,%6,%7}, {%8,%9}, {%0,%1,%2,%3};\n"
        : "+f"(c[0]), "+f"(c[1]), "+f"(c[2]), "+f"(c[3])
        : "r"(a[0]), "r"(a[1]), "r"(a[2]), "r"(a[3]), "r"(b0), "r"(b1));
}

// ============================================================
// bf16x3 GEMM core: block 128x64, BK=32, 256 thr, warp tile 32x32.
// v2: global prefetch + B-fragment reuse across mf.
// ============================================================
__device__ __forceinline__ void bf3_core(
    const float* __restrict__ A, const float* __restrict__ Bw,
    int NN, int m0, int n0, float acc[2][4][4],
    unsigned AH[128][17], unsigned AL[128][17],
    unsigned BHs[64][17], unsigned BLs[64][17])
{
    const int tid  = threadIdx.x;
    const int lane = tid & 31, wid = tid >> 5;
    const int g = lane >> 2, tig = lane & 3;
    const int wm = wid >> 1, wn = wid & 1;

    const int mA = tid >> 1, kqA = (tid & 1) * 16;
    const float* Ap = A + (size_t)(m0 + mA) * Dsz + kqA;
    const int kpB = tid >> 4, nqB = (tid & 15) * 4;
    const float* Bp = Bw + (size_t)(2 * kpB) * NN + n0 + nqB;

#pragma unroll
    for (int i = 0; i < 2; i++)
#pragma unroll
        for (int j = 0; j < 4; j++)
#pragma unroll
            for (int r = 0; r < 4; r++) acc[i][j][r] = 0.f;

    float4 a0 = *(const float4*)(Ap);
    float4 a1 = *(const float4*)(Ap + 4);
    float4 a2 = *(const float4*)(Ap + 8);
    float4 a3 = *(const float4*)(Ap + 12);
    float4 b0 = *(const float4*)(Bp);
    float4 b1 = *(const float4*)(Bp + NN);

#pragma unroll 1
    for (int it = 0; it < Dsz / 32; it++) {
        const int kp = kqA >> 1;
        splitp(a0.x, a0.y, AH[mA][kp+0], AL[mA][kp+0]);
        splitp(a0.z, a0.w, AH[mA][kp+1], AL[mA][kp+1]);
        splitp(a1.x, a1.y, AH[mA][kp+2], AL[mA][kp+2]);
        splitp(a1.z, a1.w, AH[mA][kp+3], AL[mA][kp+3]);
        splitp(a2.x, a2.y, AH[mA][kp+4], AL[mA][kp+4]);
        splitp(a2.z, a2.w, AH[mA][kp+5], AL[mA][kp+5]);
        splitp(a3.x, a3.y, AH[mA][kp+6], AL[mA][kp+6]);
        splitp(a3.z, a3.w, AH[mA][kp+7], AL[mA][kp+7]);
        splitp(b0.x, b1.x, BHs[nqB+0][kpB], BLs[nqB+0][kpB]);
        splitp(b0.y, b1.y, BHs[nqB+1][kpB], BLs[nqB+1][kpB]);
        splitp(b0.z, b1.z, BHs[nqB+2][kpB], BLs[nqB+2][kpB]);
        splitp(b0.w, b1.w, BHs[nqB+3][kpB], BLs[nqB+3][kpB]);
        __syncthreads();

        if (it + 1 < Dsz / 32) {
            const int k1 = (it + 1) * 32;
            a0 = *(const float4*)(Ap + k1);
            a1 = *(const float4*)(Ap + k1 + 4);
            a2 = *(const float4*)(Ap + k1 + 8);
            a3 = *(const float4*)(Ap + k1 + 12);
            b0 = *(const float4*)(Bp + (size_t)k1 * NN);
            b1 = *(const float4*)(Bp + (size_t)k1 * NN + NN);
        }

#pragma unroll
        for (int ks = 0; ks < 2; ks++) {
            const int kb = ks * 8;
            unsigned aH[2][4], aL[2][4];
#pragma unroll
            for (int mf = 0; mf < 2; mf++) {
                const int row = wm * 32 + mf * 16 + g;
                aH[mf][0] = AH[row][kb + tig];         aL[mf][0] = AL[row][kb + tig];
                aH[mf][1] = AH[row + 8][kb + tig];     aL[mf][1] = AL[row + 8][kb + tig];
                aH[mf][2] = AH[row][kb + 4 + tig];     aL[mf][2] = AL[row][kb + 4 + tig];
                aH[mf][3] = AH[row + 8][kb + 4 + tig]; aL[mf][3] = AL[row + 8][kb + 4 + tig];
            }
#pragma unroll
            for (int nf = 0; nf < 4; nf++) {
                const int n = wn * 32 + nf * 8 + g;
                unsigned bH0 = BHs[n][kb + tig], bH1 = BHs[n][kb + 4 + tig];
                unsigned bL0 = BLs[n][kb + tig], bL1 = BLs[n][kb + 4 + tig];
#pragma unroll
                for (int mf = 0; mf < 2; mf++) {
                    mmabf(acc[mf][nf], aL[mf], bH0, bH1);
                    mmabf(acc[mf][nf], aH[mf], bL0, bL1);
                    mmabf(acc[mf][nf], aH[mf], bH0, bH1);
                }
            }
        }
        __syncthreads();
    }
}

// ---------------- QKV GEMM -> scatter to g_Q/g_K/g_V ----------------
__global__ void __launch_bounds__(256)
qkv_b3(const float* __restrict__ A, const float* __restrict__ Bw)
{
    __shared__ unsigned AH[128][17], AL[128][17];
    __shared__ unsigned BHs[64][17], BLs[64][17];

    const int m0 = blockIdx.y * 128, n0 = blockIdx.x * 64;
    float acc[2][4][4];
    bf3_core(A, Bw, N_QKV, m0, n0, acc, AH, AL, BHs, BLs);

    const int tid = threadIdx.x;
    const int lane = tid & 31, wid = tid >> 5;
    const int g = lane >> 2, tig = lane & 3;
    const int wm = wid >> 1, wn = wid & 1;

    const int nbase = n0 + wn * 32;
    const int which = nbase / Dsz;
    const int h = (nbase % Dsz) >> 6;
    const int hd0 = (nbase % Dsz) & 63;
    float* dst = (which == 0) ? g_Q : (which == 1) ? g_K : g_V;
#pragma unroll
    for (int mf = 0; mf < 2; mf++) {
        const int m = m0 + wm * 32 + mf * 16 + g;
        const int b = m >> 11, s = m & 2047;
        float* r0 = dst + ((size_t)(b * Hsz + h) * Ssz + s) * HDsz + hd0;
        float* r1 = r0 + 8 * HDsz;
#pragma unroll
        for (int nf = 0; nf < 4; nf++) {
            const int hd = nf * 8 + tig * 2;
            *(float2*)(r0 + hd) = make_float2(acc[mf][nf][0], acc[mf][nf][1]);
            *(float2*)(r1 + hd) = make_float2(acc[mf][nf][2], acc[mf][nf][3]);
        }
    }
}

// ---------------- proj GEMM -> g_x = acc + bias + resid ----------------
__global__ void __launch_bounds__(256)
proj_b3(const float* __restrict__ Bw, const float* __restrict__ bias,
        const float* __restrict__ resid)
{
    __shared__ unsigned AH[128][17], AL[128][17];
    __shared__ unsigned BHs[64][17], BLs[64][17];

    const int m0 = blockIdx.y * 128, n0 = blockIdx.x * 64;
    float acc[2][4][4];
    bf3_core(g_attn, Bw, Dsz, m0, n0, acc, AH, AL, BHs, BLs);

    const int tid = threadIdx.x;
    const int lane = tid & 31, wid = tid >> 5;
    const int g = lane >> 2, tig = lane & 3;
    const int wm = wid >> 1, wn = wid & 1;

#pragma unroll
    for (int mf = 0; mf < 2; mf++) {
        const int m = m0 + wm * 32 + mf * 16 + g;
#pragma unroll
        for (int nf = 0; nf < 4; nf++) {
            const int n = n0 + wn * 32 + nf * 8 + tig * 2;
            float2 bv  = *(const float2*)(bias + n);
            float2 rv0 = *(const float2*)(resid + (size_t)m * Dsz + n);
            float2 rv1 = *(const float2*)(resid + (size_t)(m + 8) * Dsz + n);
            *(float2*)(g_x + (size_t)m * Dsz + n) =
                make_float2(acc[mf][nf][0] + bv.x + rv0.x, acc[mf][nf][1] + bv.y + rv0.y);
            *(float2*)(g_x + (size_t)(m + 8) * Dsz + n) =
                make_float2(acc[mf][nf][2] + bv.x + rv1.x, acc[mf][nf][3] + bv.y + rv1.y);
        }
    }
}

// ============================================================
// Flash attention, bf16x3 HMMA. 128 thr (4 warps), q-tile 128
// (warp tile 32 q-rows, mf=2), k-tile 64. Scale folded into Q.
// ============================================================
#define ATTN_SMEM_BYTES ((2*128*33 + 2*64*33 + 64*66 + 64) * 4)  // 67840 B

__global__ void __launch_bounds__(128)
fa_tc2(const float* __restrict__ pad_mask)
{
    extern __shared__ unsigned smu[];
    unsigned* QsH = smu;                     // [128][33] packed k-pairs
    unsigned* QsL = QsH + 128 * 33;
    unsigned* KsH = QsL + 128 * 33;          // [64][33]
    unsigned* KsL = KsH + 64 * 33;
    unsigned short* VtH = (unsigned short*)(KsL + 64 * 33);  // bf16 [64][66]
    unsigned short* VtL = VtH + 64 * 66;
    float* msk = (float*)(smu + 2 * 128 * 33 + 2 * 64 * 33 + 64 * 66);

    const int tid  = threadIdx.x;
    const int lane = tid & 31, wid = tid >> 5;
    const int g = lane >> 2, tig = lane & 3;
    const int qw = wid * 32;
    const int q0 = blockIdx.x * 128;
    const int bh = blockIdx.y;
    const int b = bh / Hsz, h = bh % Hsz;

    const float* Qg = g_Q + ((size_t)bh * Ssz + q0) * HDsz;
    const float* Kg = g_K + (size_t)bh * Ssz * HDsz;
    const float* Vg = g_V + (size_t)bh * Ssz * HDsz;
    const float* mk = pad_mask + b * Ssz;

    // ---- load Q tile (scaled by 1/8), split into packed hi/lo k-pairs ----
#pragma unroll
    for (int i = 0; i < 16; i++) {
        int idx = tid + i * 128;
        int r = idx >> 4, c4 = (idx & 15) * 4;
        float4 v = *(const float4*)(Qg + r * HDsz + c4);
        v.x *= 0.125f; v.y *= 0.125f; v.z *= 0.125f; v.w *= 0.125f;
        int kp = r * 33 + (c4 >> 1);
        splitp(v.x, v.y, QsH[kp],     QsL[kp]);
        splitp(v.z, v.w, QsH[kp + 1], QsL[kp + 1]);
    }

    float O[2][8][4];
#pragma unroll
    for (int mf = 0; mf < 2; mf++)
#pragma unroll
        for (int i = 0; i < 8; i++)
#pragma unroll
            for (int j = 0; j < 4; j++) O[mf][i][j] = 0.f;
    float mr0[2], mr1[2], la0[2], la1[2];
#pragma unroll
    for (int mf = 0; mf < 2; mf++) { mr0[mf] = -1e30f; mr1[mf] = -1e30f; la0[mf] = 0.f; la1[mf] = 0.f; }

#pragma unroll 1
    for (int kt = 0; kt < Ssz / 64; kt++) {
        const int key0 = kt * 64;
        __syncthreads();
#pragma unroll
        for (int i = 0; i < 8; i++) {
            int idx = tid + i * 128;
            int r = idx >> 4, c4 = (idx & 15) * 4;
            float4 kv = *(const float4*)(Kg + (size_t)(key0 + r) * HDsz + c4);
            int kp = r * 33 + (c4 >> 1);
            splitp(kv.x, kv.y, KsH[kp],     KsL[kp]);
            splitp(kv.z, kv.w, KsH[kp + 1], KsL[kp + 1]);
            float4 vv = *(const float4*)(Vg + (size_t)(key0 + r) * HDsz + c4);
#pragma unroll
            for (int q = 0; q < 4; q++) {
                float x = (&vv.x)[q];
                float hh = btrunc(x);
                VtH[(c4 + q) * 66 + r] = (unsigned short)(__float_as_uint(hh) >> 16);
                VtL[(c4 + q) * 66 + r] = (unsigned short)(__float_as_uint(btrunc(x - hh)) >> 16);
            }
        }
        if (tid < 64) msk[tid] = mk[key0 + tid];
        __syncthreads();

        // ---- S = Q @ K^T (bf16x3), 2 mf sub-tiles share K fragments ----
        float sacc[2][8][4];
#pragma unroll
        for (int mf = 0; mf < 2; mf++)
#pragma unroll
            for (int i = 0; i < 8; i++)
#pragma unroll
                for (int j = 0; j < 4; j++) sacc[mf][i][j] = 0.f;
#pragma unroll 1
        for (int ks = 0; ks < 4; ks++) {
            const int kb = ks * 8;
            unsigned aH[2][4], aL[2][4];
#pragma unroll
            for (int mf = 0; mf < 2; mf++) {
                const int row = qw + mf * 16 + g;
                aH[mf][0] = QsH[row * 33 + kb + tig];
                aH[mf][1] = QsH[(row + 8) * 33 + kb + tig];
                aH[mf][2] = QsH[row * 33 + kb + 4 + tig];
                aH[mf][3] = QsH[(row + 8) * 33 + kb + 4 + tig];
                aL[mf][0] = QsL[row * 33 + kb + tig];
                aL[mf][1] = QsL[(row + 8) * 33 + kb + tig];
                aL[mf][2] = QsL[row * 33 + kb + 4 + tig];
                aL[mf][3] = QsL[(row + 8) * 33 + kb + 4 + tig];
            }
#pragma unroll
            for (int nf = 0; nf < 8; nf++) {
                const int n = nf * 8 + g;
                unsigned bH0 = KsH[n * 33 + kb + tig];
                unsigned bH1 = KsH[n * 33 + kb + 4 + tig];
                unsigned bL0 = KsL[n * 33 + kb + tig];
                unsigned bL1 = KsL[n * 33 + kb + 4 + tig];
#pragma unroll
                for (int mf = 0; mf < 2; mf++) {
                    mmabf(sacc[mf][nf], aL[mf], bH0, bH1);
                    mmabf(sacc[mf][nf], aH[mf], bL0, bL1);
                    mmabf(sacc[mf][nf], aH[mf], bH0, bH1);
                }
            }
        }

        // ---- mask (scale already folded into Q) ----
#pragma unroll
        for (int nf = 0; nf < 8; nf++) {
            float mv0 = msk[nf * 8 + tig * 2];
            float mv1 = msk[nf * 8 + tig * 2 + 1];
#pragma unroll
            for (int mf = 0; mf < 2; mf++) {
                sacc[mf][nf][0] = sacc[mf][nf][0] * mv0 - (1.f - mv0) * 1e10f;
                sacc[mf][nf][1] = sacc[mf][nf][1] * mv1 - (1.f - mv1) * 1e10f;
                sacc[mf][nf][2] = sacc[mf][nf][2] * mv0 - (1.f - mv0) * 1e10f;
                sacc[mf][nf][3] = sacc[mf][nf][3] * mv1 - (1.f - mv1) * 1e10f;
            }
        }

        // ---- online softmax per mf (rows mf*16+g and +8) ----
#pragma unroll
        for (int mf = 0; mf < 2; mf++) {
            float tm0 = -1e30f, tm1 = -1e30f;
#pragma unroll
            for (int nf = 0; nf < 8; nf++) {
                tm0 = fmaxf(tm0, fmaxf(sacc[mf][nf][0], sacc[mf][nf][1]));
                tm1 = fmaxf(tm1, fmaxf(sacc[mf][nf][2], sacc[mf][nf][3]));
            }
            tm0 = fmaxf(tm0, __shfl_xor_sync(0xffffffffu, tm0, 1));
            tm0 = fmaxf(tm0, __shfl_xor_sync(0xffffffffu, tm0, 2));
            tm1 = fmaxf(tm1, __shfl_xor_sync(0xffffffffu, tm1, 1));
            tm1 = fmaxf(tm1, __shfl_xor_sync(0xffffffffu, tm1, 2));
            float mn0 = fmaxf(mr0[mf], tm0), mn1 = fmaxf(mr1[mf], tm1);
            float c0 = __expf(mr0[mf] - mn0), c1 = __expf(mr1[mf] - mn1);
            float s0 = 0.f, s1 = 0.f;
#pragma unroll
            for (int nf = 0; nf < 8; nf++) {
                sacc[mf][nf][0] = __expf(sacc[mf][nf][0] - mn0);
                sacc[mf][nf][1] = __expf(sacc[mf][nf][1] - mn0);
                sacc[mf][nf][2] = __expf(sacc[mf][nf][2] - mn1);
                sacc[mf][nf][3] = __expf(sacc[mf][nf][3] - mn1);
                s0 += sacc[mf][nf][0] + sacc[mf][nf][1];
                s1 += sacc[mf][nf][2] + sacc[mf][nf][3];
            }
            s0 += __shfl_xor_sync(0xffffffffu, s0, 1);
            s0 += __shfl_xor_sync(0xffffffffu, s0, 2);
            s1 += __shfl_xor_sync(0xffffffffu, s1, 1);
            s1 += __shfl_xor_sync(0xffffffffu, s1, 2);
            la0[mf] = la0[mf] * c0 + s0;
            la1[mf] = la1[mf] * c1 + s1;
            mr0[mf] = mn0; mr1[mf] = mn1;
#pragma unroll
            for (int nf = 0; nf < 8; nf++) {
                O[mf][nf][0] *= c0; O[mf][nf][1] *= c0;
                O[mf][nf][2] *= c1; O[mf][nf][3] *= c1;
            }
        }

        // ---- O += P @ V (bf16x3, P in registers, V frags shared across mf) ----
#pragma unroll 1
        for (int ks = 0; ks < 4; ks++) {
            unsigned aPH[2][4], aPL[2][4];
#pragma unroll
            for (int mf = 0; mf < 2; mf++) {
                splitp(sacc[mf][2 * ks][0],     sacc[mf][2 * ks][1],     aPH[mf][0], aPL[mf][0]);
                splitp(sacc[mf][2 * ks][2],     sacc[mf][2 * ks][3],     aPH[mf][1], aPL[mf][1]);
                splitp(sacc[mf][2 * ks + 1][0], sacc[mf][2 * ks + 1][1], aPH[mf][2], aPL[mf][2]);
                splitp(sacc[mf][2 * ks + 1][2], sacc[mf][2 * ks + 1][3], aPH[mf][3], aPL[mf][3]);
            }
            const int kb = ks * 16 + 2 * tig;
#pragma unroll
            for (int nf = 0; nf < 8; nf++) {
                const int n = nf * 8 + g;
                unsigned bH0 = *(const unsigned*)(VtH + n * 66 + kb);
                unsigned bH1 = *(const unsigned*)(VtH + n * 66 + kb + 8);
                unsigned bL0 = *(const unsigned*)(VtL + n * 66 + kb);
                unsigned bL1 = *(const unsigned*)(VtL + n * 66 + kb + 8);
#pragma unroll
                for (int mf = 0; mf < 2; mf++) {
                    mmabf(O[mf][nf], aPL[mf], bH0, bH1);
                    mmabf(O[mf][nf], aPH[mf], bL0, bL1);
                    mmabf(O[mf][nf], aPH[mf], bH0, bH1);
                }
            }
        }
    }

    // ---- epilogue -> g_attn[b,s,h*64+hd] ----
#pragma unroll
    for (int mf = 0; mf < 2; mf++) {
        const float inv0 = 1.f / la0[mf], inv1 = 1.f / la1[mf];
        const int s0r = q0 + qw + mf * 16 + g, s1r = s0r + 8;
        float* r0 = g_attn + ((size_t)b * Ssz + s0r) * Dsz + h * HDsz;
        float* r1 = g_attn + ((size_t)b * Ssz + s1r) * Dsz + h * HDsz;
#pragma unroll
        for (int nf = 0; nf < 8; nf++) {
            const int hd = nf * 8 + tig * 2;
            *(float2*)(r0 + hd) = make_float2(O[mf][nf][0] * inv0, O[mf][nf][1] * inv0);
            *(float2*)(r1 + hd) = make_float2(O[mf][nf][2] * inv1, O[mf][nf][3] * inv1);
        }
    }
}

// ---------------- LayerNorm over rows of 768 ----------------
__global__ void ln_v2(const float* __restrict__ gamma,
                      const float* __restrict__ beta,
                      float* __restrict__ out)
{
    __shared__ float red[256];
    const int row = blockIdx.x;
    const int t = threadIdx.x;
    const float* xr = g_x + (size_t)row * Dsz;

    float v[3];
    float s = 0.f;
#pragma unroll
    for (int i = 0; i < 3; i++) { v[i] = xr[t + i * 256]; s += v[i]; }
    red[t] = s; __syncthreads();
#pragma unroll
    for (int off = 128; off > 0; off >>= 1) {
        if (t < off) red[t] += red[t + off];
        __syncthreads();
    }
    float mean = red[0] * (1.f / 768.f);
    __syncthreads();

    float s2 = 0.f;
#pragma unroll
    for (int i = 0; i < 3; i++) { float d = v[i] - mean; s2 += d * d; }
    red[t] = s2; __syncthreads();
#pragma unroll
    for (int off = 128; off > 0; off >>= 1) {
        if (t < off) red[t] += red[t + off];
        __syncthreads();
    }
    float var = red[0] * (1.f / 768.f);
    float inv = rsqrtf(var + 1e-5f);

    float* orow = out + (size_t)row * Dsz;
#pragma unroll
    for (int i = 0; i < 3; i++) {
        int c = t + i * 256;
        orow[c] = (v[i] - mean) * inv * gamma[c] + beta[c];
    }
}

// ---------------- launch ----------------
extern "C" void kernel_launch(void* const* d_in, const int* in_sizes, int n_in,
                              void* d_out, int out_size)
{
    const float* context  = (const float*)d_in[0];
    const float* pad_mask = (const float*)d_in[1];
    const float* w_qkv    = (const float*)d_in[2];
    const float* w_proj   = (const float*)d_in[3];
    const float* b_proj   = (const float*)d_in[4];
    const float* gamma    = (const float*)d_in[5];
    const float* beta     = (const float*)d_in[6];
    float* out = (float*)d_out;

    cudaFuncSetAttribute(fa_tc2, cudaFuncAttributeMaxDynamicSharedMemorySize,
                         ATTN_SMEM_BYTES);

    qkv_b3<<<dim3(N_QKV / 64, MROWS / 128), 256>>>(context, w_qkv);
    fa_tc2<<<dim3(Ssz / 128, BH), 128, ATTN_SMEM_BYTES>>>(pad_mask);
    proj_b3<<<dim3(Dsz / 64, MROWS / 128), 256>>>(w_proj, b_proj, context);
    ln_v2<<<MROWS, 256>>>(gamma, beta, out);
}